// round 8
// baseline (speedup 1.0000x reference)
#include <cuda_runtime.h>
#include <cuda_bf16.h>
#include <math.h>
#include <stddef.h>

// Problem constants
#define VOCAB 32000
#define HDIM  1024
#define KDIM  512
#define VDIM  1024
#define ODIM  1024
#define NLAYER 2
#define BATCH 4
#define TSEQ  1024
#define NTOK  (BATCH * TSEQ)   // 4096

// ---------------------------------------------------------------------------
// Scratch buffers (device globals — allocation-free per harness rules)
// ---------------------------------------------------------------------------
__device__ float g_h[NTOK * HDIM];      // 16 MB : layer input/output (hidden)
__device__ float g_q[NTOK * KDIM];      //  8 MB
__device__ float g_k[NTOK * KDIM];      //  8 MB
__device__ float g_g[NTOK * KDIM];      //  8 MB
__device__ float g_v[NTOK * VDIM];      // 16 MB
__device__ float g_attn[NTOK * VDIM];   // 16 MB : scan output (pre-Wo)

// ---------------------------------------------------------------------------
// Embedding gather: h[tok][:] = emb[ids[tok]][:]
// ---------------------------------------------------------------------------
__global__ void embed_kernel(const int* __restrict__ ids,
                             const float* __restrict__ emb,
                             float* __restrict__ h)
{
    int tok = blockIdx.x;
    int id  = ids[tok];
    const float4* src = (const float4*)(emb + (size_t)id * HDIM);
    float4* dst       = (float4*)(h + (size_t)tok * HDIM);
    dst[threadIdx.x] = src[threadIdx.x];     // 256 thr * float4 = HDIM
}

// ---------------------------------------------------------------------------
// SGEMM: C[M,N] = A[M,K] @ B[K,N] + bias[N]  (optional sigmoid)
// 128x128x8 register-tiled fp32, 256 threads, TM=TN=8, double-buffered smem.
// All dims are multiples of the tile sizes (M=4096, N in {512,1024,32000},
// K in {512,1024}) -> no bounds checks.
// ---------------------------------------------------------------------------
template<int ACT>   // 0 = none, 1 = sigmoid
__global__ __launch_bounds__(256)
void sgemm_kernel(const float* __restrict__ A,
                  const float* __restrict__ B,
                  const float* __restrict__ bias,
                  float* __restrict__ C,
                  int M, int N, int K)
{
    __shared__ float As[2][8][128];   // A tile, transposed (k-major)
    __shared__ float Bs[2][8][128];

    const int tid = threadIdx.x;
    const int bx  = blockIdx.x;    // along N
    const int by  = blockIdx.y;    // along M

    const float* Ab = A + (size_t)by * 128 * K;
    const float* Bb = B + (size_t)bx * 128;

    const int aRow = tid >> 1;          // 0..127
    const int aCol = (tid & 1) * 4;     // 0 or 4
    const int bRow = tid >> 5;          // 0..7
    const int bCol = (tid & 31) * 4;    // 0..124

    const int tRow = (tid >> 4) * 8;    // 0..120
    const int tCol = (tid & 15) * 8;    // 0..120

    float acc[8][8] = {};

    // Prologue: load k-slab 0 into buffer 0
    {
        float4 av = *(const float4*)(Ab + (size_t)aRow * K + aCol);
        As[0][aCol + 0][aRow] = av.x;
        As[0][aCol + 1][aRow] = av.y;
        As[0][aCol + 2][aRow] = av.z;
        As[0][aCol + 3][aRow] = av.w;
        *(float4*)(&Bs[0][bRow][bCol]) =
            *(const float4*)(Bb + (size_t)bRow * N + bCol);
    }
    __syncthreads();

    const int nIter = K >> 3;
    int cur = 0;
    for (int it = 0; it < nIter; it++) {
        // Prefetch next slab into registers (overlaps with compute below)
        float4 av, bv;
        const bool hasNext = (it + 1 < nIter);
        if (hasNext) {
            int k0 = (it + 1) << 3;
            av = *(const float4*)(Ab + (size_t)aRow * K + k0 + aCol);
            bv = *(const float4*)(Bb + (size_t)(k0 + bRow) * N + bCol);
        }

        // Compute on current buffer
        #pragma unroll
        for (int kk = 0; kk < 8; kk++) {
            float ra[8], rb[8];
            #pragma unroll
            for (int i = 0; i < 8; i++) ra[i] = As[cur][kk][tRow + i];
            #pragma unroll
            for (int j = 0; j < 8; j++) rb[j] = Bs[cur][kk][tCol + j];
            #pragma unroll
            for (int i = 0; i < 8; i++)
                #pragma unroll
                for (int j = 0; j < 8; j++)
                    acc[i][j] += ra[i] * rb[j];
        }

        // Store prefetched slab into the other buffer (no conflict with cur)
        if (hasNext) {
            int nxt = cur ^ 1;
            As[nxt][aCol + 0][aRow] = av.x;
            As[nxt][aCol + 1][aRow] = av.y;
            As[nxt][aCol + 2][aRow] = av.z;
            As[nxt][aCol + 3][aRow] = av.w;
            *(float4*)(&Bs[nxt][bRow][bCol]) = bv;
        }
        __syncthreads();
        cur ^= 1;
    }

    // Epilogue
    #pragma unroll
    for (int i = 0; i < 8; i++) {
        size_t row = (size_t)by * 128 + tRow + i;
        float* Crow = C + row * N + (size_t)bx * 128 + tCol;
        #pragma unroll
        for (int j = 0; j < 8; j++) {
            float v = acc[i][j] + bias[(size_t)bx * 128 + tCol + j];
            if (ACT == 1) v = 1.0f / (1.0f + __expf(-v));
            Crow[j] = v;
        }
    }
}

// ---------------------------------------------------------------------------
// Gated linear-attention scan.
//   state[b,k,v] = state[b,k,v] * g_t[b,k] + k_t[b,k] * v_t[b,v]
//   out[b,t,v]   = sum_k state[b,k,v] * q_t[b,k]
//
// Grid: 128 blocks = (batch=4) x (32 v-slices of width 32).
// Block: 256 threads = 8 warps. Each warp owns 4 consecutive v values;
// lanes stride over K (lane owns k = i*32+lane, i=0..15) -> 64 state regs
// per thread, warp-shuffle butterfly reduction for the q.state dot.
// ---------------------------------------------------------------------------
__global__ __launch_bounds__(256)
void scan_kernel(const float* __restrict__ q,
                 const float* __restrict__ kk,
                 const float* __restrict__ gg,
                 const float* __restrict__ vv,
                 float* __restrict__ attn)
{
    const int b    = blockIdx.x >> 5;       // 0..3
    const int vblk = blockIdx.x & 31;       // 0..31
    const int v0   = vblk * 32;
    const int warp = threadIdx.x >> 5;      // 0..7
    const int lane = threadIdx.x & 31;
    const int myv  = v0 + warp * 4;         // 4 v per warp

    __shared__ float sq[KDIM];
    __shared__ float sk[KDIM];
    __shared__ float sg[KDIM];
    __shared__ float sv[32];

    float s[16][4];
    #pragma unroll
    for (int i = 0; i < 16; i++)
        #pragma unroll
        for (int j = 0; j < 4; j++) s[i][j] = 0.0f;

    const float* qb = q  + (size_t)b * TSEQ * KDIM;
    const float* kb = kk + (size_t)b * TSEQ * KDIM;
    const float* gb = gg + (size_t)b * TSEQ * KDIM;
    const float* vb = vv + (size_t)b * TSEQ * VDIM;

    for (int t = 0; t < TSEQ; t++) {
        const float* qt = qb + (size_t)t * KDIM;
        const float* kt = kb + (size_t)t * KDIM;
        const float* gt = gb + (size_t)t * KDIM;
        #pragma unroll
        for (int i = threadIdx.x; i < KDIM; i += 256) {
            sq[i] = qt[i];
            sk[i] = kt[i];
            sg[i] = gt[i];
        }
        if (threadIdx.x < 32)
            sv[threadIdx.x] = vb[(size_t)t * VDIM + v0 + threadIdx.x];
        __syncthreads();

        float vr0 = sv[warp * 4 + 0];
        float vr1 = sv[warp * 4 + 1];
        float vr2 = sv[warp * 4 + 2];
        float vr3 = sv[warp * 4 + 3];

        float a0 = 0.f, a1 = 0.f, a2 = 0.f, a3 = 0.f;
        #pragma unroll
        for (int i = 0; i < 16; i++) {
            int kidx = i * 32 + lane;
            float qv = sq[kidx];
            float kv = sk[kidx];
            float gv = sg[kidx];
            s[i][0] = s[i][0] * gv + kv * vr0;  a0 += s[i][0] * qv;
            s[i][1] = s[i][1] * gv + kv * vr1;  a1 += s[i][1] * qv;
            s[i][2] = s[i][2] * gv + kv * vr2;  a2 += s[i][2] * qv;
            s[i][3] = s[i][3] * gv + kv * vr3;  a3 += s[i][3] * qv;
        }

        // butterfly reduce over the 32 lanes (full K)
        #pragma unroll
        for (int off = 16; off > 0; off >>= 1) {
            a0 += __shfl_xor_sync(0xffffffffu, a0, off);
            a1 += __shfl_xor_sync(0xffffffffu, a1, off);
            a2 += __shfl_xor_sync(0xffffffffu, a2, off);
            a3 += __shfl_xor_sync(0xffffffffu, a3, off);
        }
        if (lane == 0) {
            *(float4*)&attn[((size_t)(b * TSEQ + t)) * VDIM + myv] =
                make_float4(a0, a1, a2, a3);
        }
        __syncthreads();
    }
}

// ---------------------------------------------------------------------------
// Launch
// ---------------------------------------------------------------------------
extern "C" void kernel_launch(void* const* d_in, const int* in_sizes, int n_in,
                              void* d_out, int out_size)
{
    const int*   ids    = (const int*)  d_in[0];
    const float* emb    = (const float*)d_in[1];
    const float* Wq     = (const float*)d_in[2];
    const float* bq     = (const float*)d_in[3];
    const float* Wk     = (const float*)d_in[4];
    const float* bk     = (const float*)d_in[5];
    const float* Wg     = (const float*)d_in[6];
    const float* bg     = (const float*)d_in[7];
    const float* Wv     = (const float*)d_in[8];
    const float* bv     = (const float*)d_in[9];
    const float* Wo     = (const float*)d_in[10];
    const float* bo     = (const float*)d_in[11];
    const float* W_head = (const float*)d_in[12];
    const float* b_head = (const float*)d_in[13];
    float* out = (float*)d_out;

    // Resolve scratch symbol addresses every call (no static caching — harness
    // rule). cudaGetSymbolAddress is not a stream op; safe under graph capture.
    void* p;
    float *P_H, *P_Q, *P_K, *P_G, *P_V, *P_A;
    cudaGetSymbolAddress(&p, g_h);    P_H = (float*)p;
    cudaGetSymbolAddress(&p, g_q);    P_Q = (float*)p;
    cudaGetSymbolAddress(&p, g_k);    P_K = (float*)p;
    cudaGetSymbolAddress(&p, g_g);    P_G = (float*)p;
    cudaGetSymbolAddress(&p, g_v);    P_V = (float*)p;
    cudaGetSymbolAddress(&p, g_attn); P_A = (float*)p;

    // 1) Embedding gather
    embed_kernel<<<NTOK, 256>>>(ids, emb, P_H);

    // 2) Layers
    for (int l = 0; l < NLAYER; l++) {
        const float* wq = Wq + (size_t)l * HDIM * KDIM;
        const float* wk = Wk + (size_t)l * HDIM * KDIM;
        const float* wg = Wg + (size_t)l * HDIM * KDIM;
        const float* wv = Wv + (size_t)l * HDIM * VDIM;
        const float* wo = Wo + (size_t)l * VDIM * ODIM;

        dim3 gK(KDIM / 128, NTOK / 128);   // (4, 32)
        dim3 gV(VDIM / 128, NTOK / 128);   // (8, 32)

        sgemm_kernel<0><<<gK, 256>>>(P_H, wq, bq + (size_t)l * KDIM, P_Q,
                                     NTOK, KDIM, HDIM);
        sgemm_kernel<1><<<gK, 256>>>(P_H, wk, bk + (size_t)l * KDIM, P_K,
                                     NTOK, KDIM, HDIM);
        sgemm_kernel<1><<<gK, 256>>>(P_H, wg, bg + (size_t)l * KDIM, P_G,
                                     NTOK, KDIM, HDIM);
        sgemm_kernel<0><<<gV, 256>>>(P_H, wv, bv + (size_t)l * VDIM, P_V,
                                     NTOK, VDIM, HDIM);

        scan_kernel<<<128, 256>>>(P_Q, P_K, P_G, P_V, P_A);

        sgemm_kernel<0><<<gV, 256>>>(P_A, wo, bo + (size_t)l * ODIM, P_H,
                                     NTOK, ODIM, VDIM);
    }

    // 3) Head
    dim3 gH(VOCAB / 128, NTOK / 128);      // (250, 32)
    sgemm_kernel<0><<<gH, 256>>>(P_H, W_head, b_head, out,
                                 NTOK, VOCAB, HDIM);
}